// round 14
// baseline (speedup 1.0000x reference)
#include <cuda_runtime.h>
#include <cuda_bf16.h>
#include <stdint.h>
#include <math.h>

// POVMProjector: R=32768, IN=1024, OUT=256
// d_out = [ Re(collapsed) R*1024 | probs R*256 ] (fp32) — confirmed R8.
// Split-bf16 HMMA + cp.async pipeline. This round:
//  - GEMM1 via Karatsuba 3M (P1=pr*br, P2=pim*bi, P3=(pr+pim)*(br-bi)): K 12288->9216
//  - GEMM2 single plane; ||c_im||^2 via gram matrix G=bi*bi^T appended as 256 extra N cols

#define R_TOT   32768
#define IN_DIM  1024
#define OUT_DIM 256

// ---------------- scratch ----------------
__device__ __nv_bfloat16 g_A1[(size_t)R_TOT * 6144];   // per row: [pr_h|pr_l|pim_h|pim_l|ps_h|ps_l]
__device__ __nv_bfloat16 g_B1[3 * 256 * 2048];         // plane z: rows n, [hi|lo]; z0=br, z1=bi, z2=br-bi
__device__ float         g_P[(size_t)3 * R_TOT * 256]; // P1,P2,P3 planes
__device__ __nv_bfloat16 g_A2[(size_t)R_TOT * 512];    // [p_hi|p_lo]
__device__ __nv_bfloat16 g_B2[1280 * 512];             // rows 0-1023: brT [hi|lo]; rows 1024-1279: G [hi|lo]
__device__ float         g_G[256 * 256];               // gram bi*bi^T (fp32)
__device__ float         g_c2[(size_t)R_TOT * 1280];   // cols 0-1023: c_re; 1024-1279: q = G p
__device__ float         g_nsq[(size_t)R_TOT * 16];    // c_re^2 partials

__device__ __forceinline__ uint32_t smem_u32(const void* p) {
    uint32_t a;
    asm("{ .reg .u64 t; cvta.to.shared.u64 t, %1; cvt.u32.u64 %0, t; }" : "=r"(a) : "l"(p));
    return a;
}
#define SWZ(o) ((o) ^ (((o) >> 3) & 0x70))

__device__ __forceinline__ void ldm_x4(uint32_t* r, uint32_t addr) {
    asm volatile("ldmatrix.sync.aligned.m8n8.x4.shared.b16 {%0,%1,%2,%3}, [%4];"
        : "=r"(r[0]), "=r"(r[1]), "=r"(r[2]), "=r"(r[3]) : "r"(addr));
}
__device__ __forceinline__ void mma_bf16(float* d, const uint32_t* a, const uint32_t* b) {
    asm volatile("mma.sync.aligned.m16n8k16.row.col.f32.bf16.bf16.f32 "
        "{%0,%1,%2,%3}, {%4,%5,%6,%7}, {%8,%9}, {%0,%1,%2,%3};"
        : "+f"(d[0]), "+f"(d[1]), "+f"(d[2]), "+f"(d[3])
        : "r"(a[0]), "r"(a[1]), "r"(a[2]), "r"(a[3]), "r"(b[0]), "r"(b[1]));
}
__device__ __forceinline__ void cp16(uint32_t dst, const void* src) {
    asm volatile("cp.async.cg.shared.global [%0], [%1], 16;" :: "r"(dst), "l"(src));
}
#define CP_COMMIT() asm volatile("cp.async.commit_group;" ::: "memory")
#define CP_WAIT(n)  asm volatile("cp.async.wait_group %0;" :: "n"(n) : "memory")

#define STAGE_BYTES 32768
#define NSTAGE      3
#define SM_TOTAL    (STAGE_BYTES * NSTAGE)   // 96 KB

// ---------------------------------------------------------------------------
// Generic split-bf16 HMMA GEMM.
// K-cat term order: (A_hi,B_hi) | (A_lo,B_hi) | (A_hi,B_lo).
// A physical per plane: [hi|lo] -> awrap = 2/3 of nchunks; B physical [hi|lo]
// -> bwrap = 1/3 of nchunks. Plane z: A offset z*aps (elements within row),
// B offset z*bps (global elements), C offset z*cps (global elements).
// nsq: if non-null and blockIdx.y < nsq_ymax, emit per-row sum-of-squares
// partials at slot blockIdx.y*2+wn (16 slots).
// ---------------------------------------------------------------------------
__global__ __launch_bounds__(256)
void mma_gemm(const __nv_bfloat16* __restrict__ A, int lda, int aps,
              const __nv_bfloat16* __restrict__ B, int ldb, size_t bps,
              float* __restrict__ C, int ldc, size_t cps,
              int nchunks, int awrap, int bwrap,
              float* __restrict__ nsq, int nsq_ymax)
{
    extern __shared__ __align__(1024) char smem[];

    const int tid  = threadIdx.x;
    const int lane = tid & 31, warp = tid >> 5;
    const int wm   = warp >> 1, wn = warp & 1;
    const int row0 = blockIdx.x * 128;
    const int n0   = blockIdx.y * 128;
    const int z    = blockIdx.z;

    float* Cz = C + (size_t)z * cps;

    float acc[2][8][4];
#pragma unroll
    for (int mt = 0; mt < 2; mt++)
#pragma unroll
        for (int nt = 0; nt < 8; nt++)
#pragma unroll
            for (int j = 0; j < 4; j++) acc[mt][nt][j] = 0.f;

    // loaders: 2 threads/row, 32 bf16 each
    const int lr = tid >> 1, lh = tid & 1;
    const __nv_bfloat16* gA = A + (size_t)(row0 + lr) * lda + z * aps + lh * 32;
    const __nv_bfloat16* gB = B + (size_t)z * bps + (size_t)(n0 + lr) * ldb + lh * 32;
    uint32_t stoff[4];
#pragma unroll
    for (int j = 0; j < 4; j++) stoff[j] = SWZ((uint32_t)(lr * 128 + lh * 64 + j * 16));

    const uint32_t sm0 = smem_u32(smem);

    uint32_t arow[2], brow[4];
#pragma unroll
    for (int mt = 0; mt < 2; mt++)
        arow[mt] = (uint32_t)((wm * 32 + mt * 16 + (lane & 15)) * 128 + (lane >> 4) * 16);
    {
        const int q = lane >> 3;
#pragma unroll
        for (int p = 0; p < 4; p++)
            brow[p] = (uint32_t)((wn * 64 + p * 16 + ((q & 2) ? 8 : 0) + (lane & 7)) * 128
                                 + (q & 1) * 16);
    }

    auto issue = [&](int ch, int stage) {
        const int ac = (ch >= awrap) ? ch - awrap : ch;
        const int bc = (ch >= bwrap) ? ch - bwrap : ch;
        const char* asrc = (const char*)(gA + ac * 64);
        const char* bsrc = (const char*)(gB + bc * 64);
        const uint32_t ab = sm0 + stage * STAGE_BYTES;
        const uint32_t bb = ab + 16384;
#pragma unroll
        for (int j = 0; j < 4; j++) {
            cp16(ab + stoff[j], asrc + j * 16);
            cp16(bb + stoff[j], bsrc + j * 16);
        }
        CP_COMMIT();
    };

    uint32_t afr[2][2][4];
    uint32_t bfr[2][8][2];
    auto load_frags = [&](uint32_t smA_u, uint32_t smB_u, int ks, int buf) {
#pragma unroll
        for (int mt = 0; mt < 2; mt++)
            ldm_x4(afr[buf][mt], smA_u + SWZ(arow[mt] + (uint32_t)ks * 32));
#pragma unroll
        for (int p = 0; p < 4; p++) {
            uint32_t r4[4];
            ldm_x4(r4, smB_u + SWZ(brow[p] + (uint32_t)ks * 32));
            bfr[buf][2*p][0]   = r4[0]; bfr[buf][2*p][1]   = r4[1];
            bfr[buf][2*p+1][0] = r4[2]; bfr[buf][2*p+1][1] = r4[3];
        }
    };

    issue(0, 0);
    if (nchunks > 1) issue(1, 1);

    int stage = 0;
    for (int ch = 0; ch < nchunks; ch++) {
        if (ch + 1 < nchunks) { CP_WAIT(1); } else { CP_WAIT(0); }
        __syncthreads();

        const uint32_t smA_u = sm0 + stage * STAGE_BYTES;
        const uint32_t smB_u = smA_u + 16384;

        load_frags(smA_u, smB_u, 0, 0);

        if (ch + 2 < nchunks) {
            int ns = stage + 2; if (ns >= NSTAGE) ns -= NSTAGE;
            issue(ch + 2, ns);
        }

#pragma unroll
        for (int ks = 0; ks < 4; ks++) {
            const int cur = ks & 1;
            if (ks < 3) load_frags(smA_u, smB_u, ks + 1, cur ^ 1);
#pragma unroll
            for (int mt = 0; mt < 2; mt++)
#pragma unroll
                for (int nt = 0; nt < 8; nt++)
                    mma_bf16(acc[mt][nt], afr[cur][mt], bfr[cur][nt]);
        }
        stage++; if (stage >= NSTAGE) stage -= NSTAGE;
    }

    // epilogue
    const bool do_nsq = (nsq != nullptr) && (blockIdx.y < (unsigned)nsq_ymax);
    const int gid = lane >> 2, tig = lane & 3;
#pragma unroll
    for (int mt = 0; mt < 2; mt++) {
        const int rg = row0 + wm * 32 + mt * 16 + gid;
        float s0 = 0.f, s1 = 0.f;
#pragma unroll
        for (int nt = 0; nt < 8; nt++) {
            const float a0 = acc[mt][nt][0], a1 = acc[mt][nt][1];
            const float a2 = acc[mt][nt][2], a3 = acc[mt][nt][3];
            if (do_nsq) { s0 += a0*a0 + a1*a1; s1 += a2*a2 + a3*a3; }
            const int cg = n0 + wn * 64 + nt * 8 + tig * 2;
            *(float2*)(Cz + (size_t)rg * ldc + cg)       = make_float2(a0, a1);
            *(float2*)(Cz + (size_t)(rg + 8) * ldc + cg) = make_float2(a2, a3);
        }
        if (do_nsq) {
            s0 += __shfl_xor_sync(0xffffffffu, s0, 1);
            s0 += __shfl_xor_sync(0xffffffffu, s0, 2);
            s1 += __shfl_xor_sync(0xffffffffu, s1, 1);
            s1 += __shfl_xor_sync(0xffffffffu, s1, 2);
            if (tig == 0) {
                const int slot = blockIdx.y * 2 + wn;
                g_nsq[(size_t)rg * 16 + slot]       = s0;
                g_nsq[(size_t)(rg + 8) * 16 + slot] = s1;
            }
        }
    }
}

// ---------------- conversions ----------------
__device__ __forceinline__ uint2 pack_hi4(float4 v) {
    __nv_bfloat162 a = __floats2bfloat162_rn(v.x, v.y);
    __nv_bfloat162 b = __floats2bfloat162_rn(v.z, v.w);
    uint2 r; r.x = *(uint32_t*)&a; r.y = *(uint32_t*)&b; return r;
}
__device__ __forceinline__ float4 resid4(float4 v, uint2 h) {
    __nv_bfloat162 a = *(__nv_bfloat162*)&h.x;
    __nv_bfloat162 b = *(__nv_bfloat162*)&h.y;
    return make_float4(v.x - __low2float(a), v.y - __high2float(a),
                       v.z - __low2float(b), v.w - __high2float(b));
}

// psi -> g_A1: [pr_h|pr_l|pim_h|pim_l|ps_h|ps_l], ps = pr+pim
__global__ void conv_psi(const float* __restrict__ pr, const float* __restrict__ pim)
{
    size_t i4 = (size_t)blockIdx.x * 256 + threadIdx.x;
    float4 a = ((const float4*)pr)[i4];
    float4 b = ((const float4*)pim)[i4];
    float4 s = make_float4(a.x + b.x, a.y + b.y, a.z + b.z, a.w + b.w);
    size_t row = i4 >> 8;
    int    c   = (int)(i4 & 255) * 4;
    __nv_bfloat16* rp = g_A1 + row * 6144;
    uint2 ah = pack_hi4(a), bh = pack_hi4(b), sh = pack_hi4(s);
    uint2 al = pack_hi4(resid4(a, ah));
    uint2 bl = pack_hi4(resid4(b, bh));
    uint2 sl = pack_hi4(resid4(s, sh));
    *(uint2*)(rp + c)        = ah; *(uint2*)(rp + 1024 + c) = al;
    *(uint2*)(rp + 2048 + c) = bh; *(uint2*)(rp + 3072 + c) = bl;
    *(uint2*)(rp + 4096 + c) = sh; *(uint2*)(rp + 5120 + c) = sl;
}

// basis -> g_B1 planes: z0=br, z1=bi, z2=br-bi, each rows m: [hi(1024)|lo(1024)]
__global__ void conv_basis1(const float* __restrict__ br, const float* __restrict__ bi)
{
    int idx = blockIdx.x * 256 + threadIdx.x;     // 256*1024
    int m = idx >> 10, k = idx & 1023;
    float xr = br[idx], xi = bi[idx], xd = xr - xi;
    size_t base = (size_t)m * 2048;
    __nv_bfloat16 h, l;
    h = __float2bfloat16(xr); l = __float2bfloat16(xr - __bfloat162float(h));
    g_B1[base + k] = h;  g_B1[base + 1024 + k] = l;
    h = __float2bfloat16(xi); l = __float2bfloat16(xi - __bfloat162float(h));
    g_B1[524288 + base + k] = h;  g_B1[524288 + base + 1024 + k] = l;
    h = __float2bfloat16(xd); l = __float2bfloat16(xd - __bfloat162float(h));
    g_B1[1048576 + base + k] = h; g_B1[1048576 + base + 1024 + k] = l;
}

// brT -> g_B2 rows 0-1023: row n: [br[.,n]_hi(256)|_lo(256)]
__global__ void conv_basis2(const float* __restrict__ br)
{
    int idx = blockIdx.x * 256 + threadIdx.x;     // 1024*256
    int n = idx >> 8, m = idx & 255;
    float x = br[(size_t)m * 1024 + n];
    __nv_bfloat16 h = __float2bfloat16(x);
    __nv_bfloat16 l = __float2bfloat16(x - __bfloat162float(h));
    g_B2[(size_t)n * 512 + m]       = h;
    g_B2[(size_t)n * 512 + 256 + m] = l;
}

// G (fp32) -> g_B2 rows 1024-1279: row n: [G[n,.]_hi|_lo]
__global__ void conv_G()
{
    int idx = blockIdx.x * 256 + threadIdx.x;     // 256*256
    int n = idx >> 8, m = idx & 255;
    float x = g_G[idx];
    __nv_bfloat16 h = __float2bfloat16(x);
    __nv_bfloat16 l = __float2bfloat16(x - __bfloat162float(h));
    g_B2[(size_t)(1024 + n) * 512 + m]       = h;
    g_B2[(size_t)(1024 + n) * 512 + 256 + m] = l;
}

// P1,P2,P3 -> probs (d_out tail) + g_A2 split
__global__ void probs_epi(float* __restrict__ dout)
{
    const int wid = threadIdx.x >> 5, lid = threadIdx.x & 31;
    const size_t row = (size_t)blockIdx.x * 8 + wid;
    const float4* P1 = (const float4*)(g_P + row * 256);
    const float4* P2 = (const float4*)(g_P + (size_t)R_TOT * 256 + row * 256);
    const float4* P3 = (const float4*)(g_P + (size_t)2 * R_TOT * 256 + row * 256);
    float4 p[2];
    float s = 0.f;
#pragma unroll
    for (int j = 0; j < 2; j++) {
        float4 x1 = P1[lid * 2 + j], x2 = P2[lid * 2 + j], x3 = P3[lid * 2 + j];
        float4 re = make_float4(x1.x + x2.x, x1.y + x2.y, x1.z + x2.z, x1.w + x2.w);
        float4 im = make_float4(x3.x - x1.x + x2.x, x3.y - x1.y + x2.y,
                                x3.z - x1.z + x2.z, x3.w - x1.w + x2.w);
        p[j] = make_float4(re.x*re.x + im.x*im.x, re.y*re.y + im.y*im.y,
                           re.z*re.z + im.z*im.z, re.w*re.w + im.w*im.w);
        s += p[j].x + p[j].y + p[j].z + p[j].w;
    }
#pragma unroll
    for (int off = 16; off > 0; off >>= 1) s += __shfl_xor_sync(0xffffffffu, s, off);
    const float inv = 1.f / (s + 1e-12f);
    float4 q0 = make_float4(p[0].x*inv, p[0].y*inv, p[0].z*inv, p[0].w*inv);
    float4 q1 = make_float4(p[1].x*inv, p[1].y*inv, p[1].z*inv, p[1].w*inv);
    float4* pdst = (float4*)(dout + (size_t)R_TOT * 1024 + row * 256);
    pdst[lid * 2]     = q0;
    pdst[lid * 2 + 1] = q1;
    uint2 h0 = pack_hi4(q0), h1 = pack_hi4(q1);
    uint2 l0 = pack_hi4(resid4(q0, h0)), l1 = pack_hi4(resid4(q1, h1));
    *(uint4*)(g_A2 + row * 512 + lid * 8)       = make_uint4(h0.x, h0.y, h1.x, h1.y);
    *(uint4*)(g_A2 + row * 512 + 256 + lid * 8) = make_uint4(l0.x, l0.y, l1.x, l1.y);
}

// norm^2 = sum(c_re^2 partials) + dot(p, q); out = c_re * 1/(sqrt+eps)
__global__ void norm_scale(float* __restrict__ dout)
{
    __shared__ float red[8];
    const size_t row = blockIdx.x;
    const int t = threadIdx.x, wid = t >> 5, lid = t & 31;
    const float* probs = dout + (size_t)R_TOT * 1024 + row * 256;
    float v = (t < 16) ? g_nsq[row * 16 + t] : 0.f;
    v += g_c2[row * 1280 + 1024 + t] * probs[t];
#pragma unroll
    for (int off = 16; off > 0; off >>= 1) v += __shfl_xor_sync(0xffffffffu, v, off);
    if (lid == 0) red[wid] = v;
    __syncthreads();
    float tot = red[0] + red[1] + red[2] + red[3] + red[4] + red[5] + red[6] + red[7];
    const float sc = 1.f / (sqrtf(fmaxf(tot, 0.f)) + 1e-12f);
    float4 r = ((const float4*)(g_c2 + row * 1280))[t];
    ((float4*)(dout + row * 1024))[t] =
        make_float4(r.x * sc, r.y * sc, r.z * sc, r.w * sc);
}

// ---------------------------------------------------------------------------
extern "C" void kernel_launch(void* const* d_in, const int* in_sizes, int n_in,
                              void* d_out, int out_size)
{
    const float* pr  = (const float*)d_in[0];
    const float* pim = (const float*)d_in[1];
    const float* br  = (const float*)d_in[2];
    const float* bi  = (const float*)d_in[3];
    float* out = (float*)d_out;

    cudaFuncSetAttribute(mma_gemm, cudaFuncAttributeMaxDynamicSharedMemorySize, SM_TOTAL);

    __nv_bfloat16 *a1, *b1, *a2, *b2;
    float *gP, *gG, *c2;
    cudaGetSymbolAddress((void**)&a1, g_A1);
    cudaGetSymbolAddress((void**)&b1, g_B1);
    cudaGetSymbolAddress((void**)&a2, g_A2);
    cudaGetSymbolAddress((void**)&b2, g_B2);
    cudaGetSymbolAddress((void**)&gP, g_P);
    cudaGetSymbolAddress((void**)&gG, g_G);
    cudaGetSymbolAddress((void**)&c2, g_c2);
    float* nsq;
    cudaGetSymbolAddress((void**)&nsq, g_nsq);

    // conversions
    conv_basis1<<<1024, 256>>>(br, bi);
    conv_basis2<<<1024, 256>>>(br);
    conv_psi<<<32768, 256>>>(pr, pim);

    // gram: G = bi * bi^T  (M=256, N=256, K=1024; A=B=g_B1 plane 1)
    mma_gemm<<<dim3(2, 2, 1), 256, SM_TOTAL>>>(
        b1 + 524288, 2048, 0, b1 + 524288, 2048, 0,
        gG, 256, 0, 48, 32, 16, nullptr, 0);
    conv_G<<<256, 256>>>();

    // GEMM1: P_z = A_z x B_z^T  (M=R, N=256, K=1024 split-3 => 48 chunks; 3 planes)
    mma_gemm<<<dim3(R_TOT / 128, 2, 3), 256, SM_TOTAL>>>(
        a1, 6144, 2048, b1, 2048, 524288,
        gP, 256, (size_t)R_TOT * 256, 48, 32, 16, nullptr, 0);

    // combine -> probs + split
    probs_epi<<<R_TOT / 8, 256>>>(out);

    // GEMM2: [c_re | q] = probs x [brT | G]^T  (M=R, N=1280, K=256 split-3 => 12 chunks)
    mma_gemm<<<dim3(R_TOT / 128, 10, 1), 256, SM_TOTAL>>>(
        a2, 512, 0, b2, 512, 0,
        c2, 1280, 0, 12, 8, 4, nsq, 8);

    // normalize + emit
    norm_scale<<<R_TOT, 256>>>(out);
}

// round 15
// speedup vs baseline: 1.2918x; 1.2918x over previous
#include <cuda_runtime.h>
#include <cuda_bf16.h>
#include <stdint.h>
#include <math.h>

// POVMProjector: R=32768, IN=1024, OUT=256
// d_out = [ Re(collapsed) R*1024 | probs R*256 ] (fp32) — confirmed R8.
// R15: R13 GEMM1 (4M split-bf16) + GEMM2 single plane with gram-trick
// (||c_im||^2 = p^T (bi bi^T) p via 256 extra N columns), fp32 gram kernel.

#define R_TOT   32768
#define IN_DIM  1024
#define OUT_DIM 256

// ---------------- scratch ----------------
__device__ __nv_bfloat16 g_A1[(size_t)R_TOT * 4096];     // [pr_h|pim_h|pr_l|pim_l]
__device__ __nv_bfloat16 g_B1[(size_t)2 * 256 * 6144];   // z0: re-folded, z1: im-folded (R13 layout)
__device__ float         g_I[(size_t)2 * R_TOT * 256];   // inner re, im planes
__device__ __nv_bfloat16 g_A2[(size_t)R_TOT * 512];      // [p_hi|p_lo]
__device__ __nv_bfloat16 g_B2[1280 * 512];               // rows 0-1023: brT [hi|lo]; 1024-1279: G [hi|lo]
__device__ float         g_G[256 * 256];                 // gram bi*bi^T
__device__ float         g_c2[(size_t)R_TOT * 1280];     // [c_re(1024) | q(256)]
__device__ float         g_nsq[(size_t)R_TOT * 16];      // c_re^2 partials

__device__ __forceinline__ uint32_t smem_u32(const void* p) {
    uint32_t a;
    asm("{ .reg .u64 t; cvta.to.shared.u64 t, %1; cvt.u32.u64 %0, t; }" : "=r"(a) : "l"(p));
    return a;
}
#define SWZ(o) ((o) ^ (((o) >> 3) & 0x70))

__device__ __forceinline__ void ldm_x4(uint32_t* r, uint32_t addr) {
    asm volatile("ldmatrix.sync.aligned.m8n8.x4.shared.b16 {%0,%1,%2,%3}, [%4];"
        : "=r"(r[0]), "=r"(r[1]), "=r"(r[2]), "=r"(r[3]) : "r"(addr));
}
__device__ __forceinline__ void mma_bf16(float* d, const uint32_t* a, const uint32_t* b) {
    asm volatile("mma.sync.aligned.m16n8k16.row.col.f32.bf16.bf16.f32 "
        "{%0,%1,%2,%3}, {%4,%5,%6,%7}, {%8,%9}, {%0,%1,%2,%3};"
        : "+f"(d[0]), "+f"(d[1]), "+f"(d[2]), "+f"(d[3])
        : "r"(a[0]), "r"(a[1]), "r"(a[2]), "r"(a[3]), "r"(b[0]), "r"(b[1]));
}
__device__ __forceinline__ void cp16(uint32_t dst, const void* src) {
    asm volatile("cp.async.cg.shared.global [%0], [%1], 16;" :: "r"(dst), "l"(src));
}
#define CP_COMMIT() asm volatile("cp.async.commit_group;" ::: "memory")
#define CP_WAIT(n)  asm volatile("cp.async.wait_group %0;" :: "n"(n) : "memory")

#define STAGE_BYTES 32768
#define NSTAGE      3
#define SM_TOTAL    (STAGE_BYTES * NSTAGE)   // 96 KB

// ---------------------------------------------------------------------------
// Generic split-bf16 HMMA GEMM (verified in R13/R14).
// Plane z: A col offset z*aps, B offset z*bps, C offset z*cps.
// Chunk ch: A col (ch>=awrap? ch-awrap: ch)*64; B col (ch>=bwrap? ch-bwrap: ch)*64.
// nsq: if non-null and blockIdx.y < nsq_ymax, per-row sum-of-squares partials.
// ---------------------------------------------------------------------------
__global__ __launch_bounds__(256)
void mma_gemm(const __nv_bfloat16* __restrict__ A, int lda, int aps,
              const __nv_bfloat16* __restrict__ B, int ldb, size_t bps,
              float* __restrict__ C, int ldc, size_t cps,
              int nchunks, int awrap, int bwrap,
              float* __restrict__ nsq, int nsq_ymax)
{
    extern __shared__ __align__(1024) char smem[];

    const int tid  = threadIdx.x;
    const int lane = tid & 31, warp = tid >> 5;
    const int wm   = warp >> 1, wn = warp & 1;
    const int row0 = blockIdx.x * 128;
    const int n0   = blockIdx.y * 128;
    const int z    = blockIdx.z;

    float* Cz = C + (size_t)z * cps;

    float acc[2][8][4];
#pragma unroll
    for (int mt = 0; mt < 2; mt++)
#pragma unroll
        for (int nt = 0; nt < 8; nt++)
#pragma unroll
            for (int j = 0; j < 4; j++) acc[mt][nt][j] = 0.f;

    const int lr = tid >> 1, lh = tid & 1;
    const __nv_bfloat16* gA = A + (size_t)(row0 + lr) * lda + z * aps + lh * 32;
    const __nv_bfloat16* gB = B + (size_t)z * bps + (size_t)(n0 + lr) * ldb + lh * 32;
    uint32_t stoff[4];
#pragma unroll
    for (int j = 0; j < 4; j++) stoff[j] = SWZ((uint32_t)(lr * 128 + lh * 64 + j * 16));

    const uint32_t sm0 = smem_u32(smem);

    uint32_t arow[2], brow[4];
#pragma unroll
    for (int mt = 0; mt < 2; mt++)
        arow[mt] = (uint32_t)((wm * 32 + mt * 16 + (lane & 15)) * 128 + (lane >> 4) * 16);
    {
        const int q = lane >> 3;
#pragma unroll
        for (int p = 0; p < 4; p++)
            brow[p] = (uint32_t)((wn * 64 + p * 16 + ((q & 2) ? 8 : 0) + (lane & 7)) * 128
                                 + (q & 1) * 16);
    }

    auto issue = [&](int ch, int stage) {
        const int ac = (ch >= awrap) ? ch - awrap : ch;
        const int bc = (ch >= bwrap) ? ch - bwrap : ch;
        const char* asrc = (const char*)(gA + ac * 64);
        const char* bsrc = (const char*)(gB + bc * 64);
        const uint32_t ab = sm0 + stage * STAGE_BYTES;
        const uint32_t bb = ab + 16384;
#pragma unroll
        for (int j = 0; j < 4; j++) {
            cp16(ab + stoff[j], asrc + j * 16);
            cp16(bb + stoff[j], bsrc + j * 16);
        }
        CP_COMMIT();
    };

    uint32_t afr[2][2][4];
    uint32_t bfr[2][8][2];
    auto load_frags = [&](uint32_t smA_u, uint32_t smB_u, int ks, int buf) {
#pragma unroll
        for (int mt = 0; mt < 2; mt++)
            ldm_x4(afr[buf][mt], smA_u + SWZ(arow[mt] + (uint32_t)ks * 32));
#pragma unroll
        for (int p = 0; p < 4; p++) {
            uint32_t r4[4];
            ldm_x4(r4, smB_u + SWZ(brow[p] + (uint32_t)ks * 32));
            bfr[buf][2*p][0]   = r4[0]; bfr[buf][2*p][1]   = r4[1];
            bfr[buf][2*p+1][0] = r4[2]; bfr[buf][2*p+1][1] = r4[3];
        }
    };

    issue(0, 0);
    if (nchunks > 1) issue(1, 1);

    int stage = 0;
    for (int ch = 0; ch < nchunks; ch++) {
        if (ch + 1 < nchunks) { CP_WAIT(1); } else { CP_WAIT(0); }
        __syncthreads();

        const uint32_t smA_u = sm0 + stage * STAGE_BYTES;
        const uint32_t smB_u = smA_u + 16384;

        load_frags(smA_u, smB_u, 0, 0);

        if (ch + 2 < nchunks) {
            int ns = stage + 2; if (ns >= NSTAGE) ns -= NSTAGE;
            issue(ch + 2, ns);
        }

#pragma unroll
        for (int ks = 0; ks < 4; ks++) {
            const int cur = ks & 1;
            if (ks < 3) load_frags(smA_u, smB_u, ks + 1, cur ^ 1);
#pragma unroll
            for (int mt = 0; mt < 2; mt++)
#pragma unroll
                for (int nt = 0; nt < 8; nt++)
                    mma_bf16(acc[mt][nt], afr[cur][mt], bfr[cur][nt]);
        }
        stage++; if (stage >= NSTAGE) stage -= NSTAGE;
    }

    const bool do_nsq = (nsq != nullptr) && (blockIdx.y < (unsigned)nsq_ymax);
    const int gid = lane >> 2, tig = lane & 3;
#pragma unroll
    for (int mt = 0; mt < 2; mt++) {
        const int rg = row0 + wm * 32 + mt * 16 + gid;
        float s0 = 0.f, s1 = 0.f;
#pragma unroll
        for (int nt = 0; nt < 8; nt++) {
            const float a0 = acc[mt][nt][0], a1 = acc[mt][nt][1];
            const float a2 = acc[mt][nt][2], a3 = acc[mt][nt][3];
            if (do_nsq) { s0 += a0*a0 + a1*a1; s1 += a2*a2 + a3*a3; }
            const int cg = n0 + wn * 64 + nt * 8 + tig * 2;
            *(float2*)(Cz + (size_t)rg * ldc + cg)       = make_float2(a0, a1);
            *(float2*)(Cz + (size_t)(rg + 8) * ldc + cg) = make_float2(a2, a3);
        }
        if (do_nsq) {
            s0 += __shfl_xor_sync(0xffffffffu, s0, 1);
            s0 += __shfl_xor_sync(0xffffffffu, s0, 2);
            s1 += __shfl_xor_sync(0xffffffffu, s1, 1);
            s1 += __shfl_xor_sync(0xffffffffu, s1, 2);
            if (tig == 0) {
                const int slot = blockIdx.y * 2 + wn;
                g_nsq[(size_t)rg * 16 + slot]       = s0;
                g_nsq[(size_t)(rg + 8) * 16 + slot] = s1;
            }
        }
    }
}

// ---------------- gram: G = bi * bi^T (fp32, 16 CTAs, ~10us) ----------------
__global__ void gram_fp32(const float* __restrict__ bi)
{
    __shared__ float Sn[64][65];
    __shared__ float Sm[64][65];
    const int tx = threadIdx.x, ty = threadIdx.y;       // 16x16
    const int t  = ty * 16 + tx;
    const int n0 = blockIdx.x * 64, m0 = blockIdx.y * 64;

    float acc[4][4] = {};
    for (int k0 = 0; k0 < 1024; k0 += 64) {
        __syncthreads();
#pragma unroll
        for (int j = 0; j < 16; j++) {
            int idx = t + j * 256;             // 0..4095
            int r = idx >> 6, c = idx & 63;
            Sn[r][c] = bi[(size_t)(n0 + r) * 1024 + k0 + c];
            Sm[r][c] = bi[(size_t)(m0 + r) * 1024 + k0 + c];
        }
        __syncthreads();
#pragma unroll 8
        for (int k = 0; k < 64; k++) {
            float a[4], b[4];
#pragma unroll
            for (int i = 0; i < 4; i++) { a[i] = Sn[ty * 4 + i][k]; b[i] = Sm[tx * 4 + i][k]; }
#pragma unroll
            for (int i = 0; i < 4; i++)
#pragma unroll
                for (int j = 0; j < 4; j++) acc[i][j] = fmaf(a[i], b[j], acc[i][j]);
        }
    }
#pragma unroll
    for (int i = 0; i < 4; i++)
#pragma unroll
        for (int j = 0; j < 4; j++)
            g_G[(size_t)(n0 + ty * 4 + i) * 256 + m0 + tx * 4 + j] = acc[i][j];
}

// ---------------- conversions ----------------
__device__ __forceinline__ uint2 pack_hi4(float4 v) {
    __nv_bfloat162 a = __floats2bfloat162_rn(v.x, v.y);
    __nv_bfloat162 b = __floats2bfloat162_rn(v.z, v.w);
    uint2 r; r.x = *(uint32_t*)&a; r.y = *(uint32_t*)&b; return r;
}
__device__ __forceinline__ float4 resid4(float4 v, uint2 h) {
    __nv_bfloat162 a = *(__nv_bfloat162*)&h.x;
    __nv_bfloat162 b = *(__nv_bfloat162*)&h.y;
    return make_float4(v.x - __low2float(a), v.y - __high2float(a),
                       v.z - __low2float(b), v.w - __high2float(b));
}

__global__ void conv_psi(const float* __restrict__ pr, const float* __restrict__ pim)
{
    size_t i4 = (size_t)blockIdx.x * 256 + threadIdx.x;
    float4 a = ((const float4*)pr)[i4];
    float4 b = ((const float4*)pim)[i4];
    size_t row = i4 >> 8;
    int    c   = (int)(i4 & 255) * 4;
    __nv_bfloat16* rp = g_A1 + row * 4096;
    uint2 ah = pack_hi4(a), bh = pack_hi4(b);
    uint2 al = pack_hi4(resid4(a, ah)), bl = pack_hi4(resid4(b, bh));
    *(uint2*)(rp + c)        = ah;
    *(uint2*)(rp + 1024 + c) = bh;
    *(uint2*)(rp + 2048 + c) = al;
    *(uint2*)(rp + 3072 + c) = bl;
}

// basis -> g_B1 planes (R13 content): z0 = [br_h|bi_h|br_h|bi_h|br_l|bi_l],
// z1 = [-bi_h|br_h|-bi_h|br_h|-bi_l|br_l]
__global__ void conv_basis1(const float* __restrict__ br, const float* __restrict__ bi)
{
    int idx = blockIdx.x * 256 + threadIdx.x;
    int m = idx >> 10, k = idx & 1023;
    float xr = br[idx], xi = bi[idx];
    __nv_bfloat16 rh = __float2bfloat16(xr);
    __nv_bfloat16 rl = __float2bfloat16(xr - __bfloat162float(rh));
    __nv_bfloat16 ih = __float2bfloat16(xi);
    __nv_bfloat16 il = __float2bfloat16(xi - __bfloat162float(ih));
    __nv_bfloat16 nih = __float2bfloat16(-xi);
    __nv_bfloat16 nil = __float2bfloat16(-xi - __bfloat162float(nih));
    size_t base = (size_t)m * 6144;
    __nv_bfloat16* B0 = g_B1;
    __nv_bfloat16* B1 = g_B1 + (size_t)256 * 6144;
    B0[base + k]        = rh;  B0[base + 1024 + k] = ih;
    B0[base + 2048 + k] = rh;  B0[base + 3072 + k] = ih;
    B0[base + 4096 + k] = rl;  B0[base + 5120 + k] = il;
    B1[base + k]        = nih; B1[base + 1024 + k] = rh;
    B1[base + 2048 + k] = nih; B1[base + 3072 + k] = rh;
    B1[base + 4096 + k] = nil; B1[base + 5120 + k] = rl;
}

// brT -> g_B2 rows 0-1023
__global__ void conv_basis2(const float* __restrict__ br)
{
    int idx = blockIdx.x * 256 + threadIdx.x;
    int n = idx >> 8, m = idx & 255;
    float x = br[(size_t)m * 1024 + n];
    __nv_bfloat16 h = __float2bfloat16(x);
    __nv_bfloat16 l = __float2bfloat16(x - __bfloat162float(h));
    g_B2[(size_t)n * 512 + m]       = h;
    g_B2[(size_t)n * 512 + 256 + m] = l;
}

// G -> g_B2 rows 1024-1279
__global__ void conv_G()
{
    int idx = blockIdx.x * 256 + threadIdx.x;
    int n = idx >> 8, m = idx & 255;
    float x = g_G[idx];
    __nv_bfloat16 h = __float2bfloat16(x);
    __nv_bfloat16 l = __float2bfloat16(x - __bfloat162float(h));
    g_B2[(size_t)(1024 + n) * 512 + m]       = h;
    g_B2[(size_t)(1024 + n) * 512 + 256 + m] = l;
}

// inner planes -> probs (d_out tail) + g_A2 split
__global__ void probs_epi(float* __restrict__ dout)
{
    const int wid = threadIdx.x >> 5, lid = threadIdx.x & 31;
    const size_t row = (size_t)blockIdx.x * 8 + wid;
    const float4* re = (const float4*)(g_I + row * 256);
    const float4* im = (const float4*)(g_I + (size_t)R_TOT * 256 + row * 256);
    float4 r0 = re[lid * 2], r1 = re[lid * 2 + 1];
    float4 i0 = im[lid * 2], i1 = im[lid * 2 + 1];
    float4 p0 = make_float4(r0.x*r0.x + i0.x*i0.x, r0.y*r0.y + i0.y*i0.y,
                            r0.z*r0.z + i0.z*i0.z, r0.w*r0.w + i0.w*i0.w);
    float4 p1 = make_float4(r1.x*r1.x + i1.x*i1.x, r1.y*r1.y + i1.y*i1.y,
                            r1.z*r1.z + i1.z*i1.z, r1.w*r1.w + i1.w*i1.w);
    float s = p0.x + p0.y + p0.z + p0.w + p1.x + p1.y + p1.z + p1.w;
#pragma unroll
    for (int off = 16; off > 0; off >>= 1) s += __shfl_xor_sync(0xffffffffu, s, off);
    const float inv = 1.f / (s + 1e-12f);
    float4 q0 = make_float4(p0.x*inv, p0.y*inv, p0.z*inv, p0.w*inv);
    float4 q1 = make_float4(p1.x*inv, p1.y*inv, p1.z*inv, p1.w*inv);
    float4* pdst = (float4*)(dout + (size_t)R_TOT * 1024 + row * 256);
    pdst[lid * 2]     = q0;
    pdst[lid * 2 + 1] = q1;
    uint2 h0 = pack_hi4(q0), h1 = pack_hi4(q1);
    uint2 l0 = pack_hi4(resid4(q0, h0)), l1 = pack_hi4(resid4(q1, h1));
    *(uint4*)(g_A2 + row * 512 + lid * 8)       = make_uint4(h0.x, h0.y, h1.x, h1.y);
    *(uint4*)(g_A2 + row * 512 + 256 + lid * 8) = make_uint4(l0.x, l0.y, l1.x, l1.y);
}

// norm^2 = sum(c_re^2 partials) + dot(probs, q); out = c_re/(sqrt+eps)
__global__ void norm_scale(float* __restrict__ dout)
{
    __shared__ float red[8];
    const size_t row = blockIdx.x;
    const int t = threadIdx.x, wid = t >> 5, lid = t & 31;
    const float* probs = dout + (size_t)R_TOT * 1024 + row * 256;
    float v = (t < 16) ? g_nsq[row * 16 + t] : 0.f;
    v += g_c2[row * 1280 + 1024 + t] * probs[t];
#pragma unroll
    for (int off = 16; off > 0; off >>= 1) v += __shfl_xor_sync(0xffffffffu, v, off);
    if (lid == 0) red[wid] = v;
    __syncthreads();
    float tot = red[0] + red[1] + red[2] + red[3] + red[4] + red[5] + red[6] + red[7];
    const float sc = 1.f / (sqrtf(fmaxf(tot, 0.f)) + 1e-12f);
    float4 r = ((const float4*)(g_c2 + row * 1280))[t];
    ((float4*)(dout + row * 1024))[t] =
        make_float4(r.x * sc, r.y * sc, r.z * sc, r.w * sc);
}

// ---------------------------------------------------------------------------
extern "C" void kernel_launch(void* const* d_in, const int* in_sizes, int n_in,
                              void* d_out, int out_size)
{
    const float* pr  = (const float*)d_in[0];
    const float* pim = (const float*)d_in[1];
    const float* br  = (const float*)d_in[2];
    const float* bi  = (const float*)d_in[3];
    float* out = (float*)d_out;

    static int smem_set = 0;
    if (!smem_set) {
        cudaFuncSetAttribute(mma_gemm, cudaFuncAttributeMaxDynamicSharedMemorySize, SM_TOTAL);
        smem_set = 1;
    }

    __nv_bfloat16 *a1, *b1, *a2, *b2;
    float *gI, *c2, *nsq;
    cudaGetSymbolAddress((void**)&a1, g_A1);
    cudaGetSymbolAddress((void**)&b1, g_B1);
    cudaGetSymbolAddress((void**)&a2, g_A2);
    cudaGetSymbolAddress((void**)&b2, g_B2);
    cudaGetSymbolAddress((void**)&gI, g_I);
    cudaGetSymbolAddress((void**)&c2, g_c2);
    cudaGetSymbolAddress((void**)&nsq, g_nsq);

    // conversions + gram (gram reads raw bi; tiny)
    gram_fp32<<<dim3(4, 4), dim3(16, 16)>>>(bi);
    conv_basis1<<<1024, 256>>>(br, bi);
    conv_basis2<<<1024, 256>>>(br);
    conv_G<<<256, 256>>>();
    conv_psi<<<32768, 256>>>(pr, pim);

    // GEMM1 (R13 form): inner planes = psi x folded-basis^T
    // M=R, N=256/plane, K-cat 96 chunks (awrap=64, B no wrap), z in {re, im}
    mma_gemm<<<dim3(R_TOT / 128, 2, 2), 256, SM_TOTAL>>>(
        a1, 4096, 0, b1, 6144, (size_t)256 * 6144,
        gI, 256, (size_t)R_TOT * 256, 96, 64, 96, nullptr, 0);

    // probs + split
    probs_epi<<<R_TOT / 8, 256>>>(out);

    // GEMM2: [c_re | q] = probs x [brT | G]^T  (N=1280, 12 chunks, awrap=8, bwrap=4)
    mma_gemm<<<dim3(R_TOT / 128, 10, 1), 256, SM_TOTAL>>>(
        a2, 512, 0, b2, 512, 0,
        c2, 1280, 0, 12, 8, 4, nsq, 8);

    // normalize + emit
    norm_scale<<<R_TOT, 256>>>(out);
}